// round 1
// baseline (speedup 1.0000x reference)
#include <cuda_runtime.h>

// Problem constants
#define BT   8192      // B*T = 4*2048
#define TT   2048      // T
#define NB   4         // B
#define Dm   2048      // D
#define KD   1024      // Kdim = H*DK
#define VD   2048      // Vdim = H*DV

// Scratch (device globals: allocation-free rule)
__device__ float g_x[BT * Dm];      // 64 MiB  normalized input
__device__ float g_g1[BT * 16];     // x @ Wg1
__device__ float g_e[BT * KD];      // Gcum, then exp(Gtot - Gcum)
__device__ float g_k[BT * KD];      // ktilde = (x@Wk) * e
__device__ float g_v[BT * VD];      // x @ Wv
__device__ float g_gtot[NB * KD];   // Gtot per (b, h*128+kk)

// ---------------------------------------------------------------------------
// Kernel 1: RMSNorm (+ norm_w) and g1 = x @ Wg1   (one block per row)
// ---------------------------------------------------------------------------
__global__ __launch_bounds__(256) void k_rmsnorm(const float* __restrict__ seg,
                                                 const float* __restrict__ nw,
                                                 const float* __restrict__ Wg1) {
    int row = blockIdx.x;
    int tid = threadIdx.x;
    const float4* s4 = (const float4*)(seg + (size_t)row * Dm);
    float4 v0 = s4[tid];
    float4 v1 = s4[tid + 256];
    float ss = v0.x*v0.x + v0.y*v0.y + v0.z*v0.z + v0.w*v0.w
             + v1.x*v1.x + v1.y*v1.y + v1.z*v1.z + v1.w*v1.w;
    #pragma unroll
    for (int o = 16; o; o >>= 1) ss += __shfl_xor_sync(0xffffffffu, ss, o);
    __shared__ float sred[8];
    int wid = tid >> 5, lane = tid & 31;
    if (lane == 0) sred[wid] = ss;
    __syncthreads();
    float tot = 0.f;
    #pragma unroll
    for (int w = 0; w < 8; w++) tot += sred[w];
    float rinv = rsqrtf(tot * (1.0f / Dm) + 1e-5f);

    const float4* w4 = (const float4*)nw;
    float4 n0 = w4[tid], n1 = w4[tid + 256];
    float4 x0, x1;
    x0.x = v0.x*rinv*n0.x; x0.y = v0.y*rinv*n0.y; x0.z = v0.z*rinv*n0.z; x0.w = v0.w*rinv*n0.w;
    x1.x = v1.x*rinv*n1.x; x1.y = v1.y*rinv*n1.y; x1.z = v1.z*rinv*n1.z; x1.w = v1.w*rinv*n1.w;
    float4* xo = (float4*)(g_x + (size_t)row * Dm);
    xo[tid] = x0;
    xo[tid + 256] = x1;

    // g1 partial: this thread owns x elements [tid*4, tid*4+4) and [1024+tid*4, ...)
    float p[16];
    #pragma unroll
    for (int j = 0; j < 16; j++) p[j] = 0.f;
    float xa[4] = {x0.x, x0.y, x0.z, x0.w};
    float xb[4] = {x1.x, x1.y, x1.z, x1.w};
    #pragma unroll
    for (int i = 0; i < 4; i++) {
        const float* wg = Wg1 + (size_t)(tid * 4 + i) * 16;
        #pragma unroll
        for (int j = 0; j < 16; j++) p[j] += xa[i] * wg[j];
    }
    #pragma unroll
    for (int i = 0; i < 4; i++) {
        const float* wg = Wg1 + (size_t)(1024 + tid * 4 + i) * 16;
        #pragma unroll
        for (int j = 0; j < 16; j++) p[j] += xb[i] * wg[j];
    }
    #pragma unroll
    for (int o = 16; o; o >>= 1) {
        #pragma unroll
        for (int j = 0; j < 16; j++) p[j] += __shfl_xor_sync(0xffffffffu, p[j], o);
    }
    __shared__ float pg[8][16];
    if (lane == 0) {
        #pragma unroll
        for (int j = 0; j < 16; j++) pg[wid][j] = p[j];
    }
    __syncthreads();
    if (tid < 16) {
        float s = 0.f;
        #pragma unroll
        for (int w = 0; w < 8; w++) s += pg[w][tid];
        g_g1[row * 16 + tid] = s;
    }
}

// ---------------------------------------------------------------------------
// Kernel 2: per-(b,h,k) gate cumsum:  Gcum stored to g_e, Gtot to g_gtot
// one block per (b,h), 128 threads (one per k dim)
// ---------------------------------------------------------------------------
__global__ __launch_bounds__(128) void k_gate(const float* __restrict__ Wg2,
                                              const float* __restrict__ bg2) {
    int bh = blockIdx.x;
    int b = bh >> 3, h = bh & 7;
    int kk = threadIdx.x;
    int col = h * 128 + kk;
    float w[16];
    #pragma unroll
    for (int j = 0; j < 16; j++) w[j] = Wg2[j * KD + col];
    float bias = bg2[col];
    float cum = 0.f;
    __shared__ float sh[2048];  // 128 g1 rows x 16
    const float* g1b = g_g1 + (size_t)b * TT * 16;
    float* eb = g_e + (size_t)b * TT * KD + col;
    for (int t0 = 0; t0 < TT; t0 += 128) {
        __syncthreads();
        const float4* src = (const float4*)(g1b + (size_t)t0 * 16);
        #pragma unroll
        for (int l = 0; l < 4; l++)
            ((float4*)sh)[threadIdx.x + l * 128] = src[threadIdx.x + l * 128];
        __syncthreads();
        for (int tt = 0; tt < 128; tt++) {
            float z = bias;
            #pragma unroll
            for (int j = 0; j < 16; j++) z += sh[tt * 16 + j] * w[j];
            // log_sigmoid(z), numerically stable
            float ls = (z >= 0.f) ? -log1pf(__expf(-z)) : (z - log1pf(__expf(z)));
            cum += ls * (1.0f / 16.0f);
            eb[(size_t)(t0 + tt) * KD] = cum;
        }
    }
    g_gtot[bh * 128 + kk] = cum;
}

// ---------------------------------------------------------------------------
// Kernel 2b: elementwise e = exp(Gtot - Gcum)
// ---------------------------------------------------------------------------
__global__ __launch_bounds__(256) void k_exp() {
    size_t i = (size_t)blockIdx.x * 256 + threadIdx.x;  // over BT*KD = 2^23
    int b = (int)(i >> 21);           // / (2048*1024)
    int col = (int)(i & 1023);
    g_e[i] = expf(g_gtot[(b << 10) | col] - g_e[i]);
}

// ---------------------------------------------------------------------------
// Kernel 3: SGEMM  C[8192xN] = g_x[8192x2048] @ W[2048xN]
// WHICH==0: N=1024, C=g_k, epilogue *= g_e.   WHICH==1: N=2048, C=g_v.
// 128x128 tile, BK=16, 8x8 per thread, 256 threads
// ---------------------------------------------------------------------------
template <int WHICH>
__global__ __launch_bounds__(256) void k_sgemm(const float* __restrict__ W) {
    constexpr int N = (WHICH == 0) ? KD : VD;
    float* __restrict__ C = (WHICH == 0) ? g_k : g_v;
    const int K = Dm;
    __shared__ __align__(16) float As[16][128];
    __shared__ __align__(16) float Bs[16][128];
    int tid = threadIdx.x;
    int tx = tid & 15, ty = tid >> 4;
    const float* Ab = g_x + (size_t)blockIdx.y * 128 * K;
    const float* Wb = W + blockIdx.x * 128;
    float acc[8][8];
    #pragma unroll
    for (int i = 0; i < 8; i++)
        #pragma unroll
        for (int j = 0; j < 8; j++) acc[i][j] = 0.f;

    for (int k0 = 0; k0 < K; k0 += 16) {
        #pragma unroll
        for (int l = 0; l < 2; l++) {
            int f = tid + l * 256;
            int r = f >> 2, c = (f & 3) * 4;
            float4 va = *(const float4*)(Ab + (size_t)r * K + k0 + c);
            As[c + 0][r] = va.x; As[c + 1][r] = va.y;
            As[c + 2][r] = va.z; As[c + 3][r] = va.w;
            int rb = f >> 5, cb = (f & 31) * 4;
            *(float4*)&Bs[rb][cb] = *(const float4*)(Wb + (size_t)(k0 + rb) * N + cb);
        }
        __syncthreads();
        #pragma unroll
        for (int kk = 0; kk < 16; kk++) {
            float4 a0 = *(const float4*)&As[kk][ty * 8];
            float4 a1 = *(const float4*)&As[kk][ty * 8 + 4];
            float4 b0 = *(const float4*)&Bs[kk][tx * 8];
            float4 b1 = *(const float4*)&Bs[kk][tx * 8 + 4];
            float a[8] = {a0.x, a0.y, a0.z, a0.w, a1.x, a1.y, a1.z, a1.w};
            float bb[8] = {b0.x, b0.y, b0.z, b0.w, b1.x, b1.y, b1.z, b1.w};
            #pragma unroll
            for (int i = 0; i < 8; i++)
                #pragma unroll
                for (int j = 0; j < 8; j++) acc[i][j] += a[i] * bb[j];
        }
        __syncthreads();
    }
    #pragma unroll
    for (int i = 0; i < 8; i++) {
        size_t row = (size_t)blockIdx.y * 128 + ty * 8 + i;
        #pragma unroll
        for (int j4 = 0; j4 < 2; j4++) {
            int col = blockIdx.x * 128 + tx * 8 + j4 * 4;
            float4 r;
            r.x = acc[i][j4 * 4 + 0]; r.y = acc[i][j4 * 4 + 1];
            r.z = acc[i][j4 * 4 + 2]; r.w = acc[i][j4 * 4 + 3];
            if (WHICH == 0) {
                float4 e = *(const float4*)(g_e + row * N + col);
                r.x *= e.x; r.y *= e.y; r.z *= e.z; r.w *= e.w;
            }
            *(float4*)(C + row * N + col) = r;
        }
    }
}

// ---------------------------------------------------------------------------
// Kernel 4a: out = initial_state * exp(Gtot)   (also clears the poison)
// ---------------------------------------------------------------------------
__global__ __launch_bounds__(256) void k_init(const float* __restrict__ init,
                                              float* __restrict__ out) {
    int i = blockIdx.x * 256 + threadIdx.x;  // 4*8*128*256 = 2^20
    out[i] = init[i] * expf(g_gtot[i >> 8]);
}

// ---------------------------------------------------------------------------
// Kernel 4b: S[bh] += ktilde_bh^T[128x2048] @ v_bh[2048x256]
// grid: (vtile=2, bh=32, kseg=8); split-K over t with atomicAdd
// ---------------------------------------------------------------------------
__global__ __launch_bounds__(256) void k_state(float* __restrict__ out) {
    int bh = blockIdx.y;
    int b = bh >> 3, h = bh & 7;
    int tseg0 = blockIdx.z * 256;
    __shared__ __align__(16) float As[16][128];  // [t][kk]
    __shared__ __align__(16) float Bs[16][128];  // [t][vv]
    const float* Abase = g_k + (size_t)b * TT * KD + h * 128;
    const float* Bbase = g_v + (size_t)b * TT * VD + h * 256 + blockIdx.x * 128;
    int tid = threadIdx.x;
    int tx = tid & 15, ty = tid >> 4;
    float acc[8][8];
    #pragma unroll
    for (int i = 0; i < 8; i++)
        #pragma unroll
        for (int j = 0; j < 8; j++) acc[i][j] = 0.f;

    for (int t0 = tseg0; t0 < tseg0 + 256; t0 += 16) {
        #pragma unroll
        for (int l = 0; l < 2; l++) {
            int f = tid + l * 256;
            int r = f >> 5, c = (f & 31) * 4;
            *(float4*)&As[r][c] = *(const float4*)(Abase + (size_t)(t0 + r) * KD + c);
            *(float4*)&Bs[r][c] = *(const float4*)(Bbase + (size_t)(t0 + r) * VD + c);
        }
        __syncthreads();
        #pragma unroll
        for (int tt = 0; tt < 16; tt++) {
            float4 a0 = *(const float4*)&As[tt][ty * 8];
            float4 a1 = *(const float4*)&As[tt][ty * 8 + 4];
            float4 b0 = *(const float4*)&Bs[tt][tx * 8];
            float4 b1 = *(const float4*)&Bs[tt][tx * 8 + 4];
            float a[8] = {a0.x, a0.y, a0.z, a0.w, a1.x, a1.y, a1.z, a1.w};
            float bb[8] = {b0.x, b0.y, b0.z, b0.w, b1.x, b1.y, b1.z, b1.w};
            #pragma unroll
            for (int i = 0; i < 8; i++)
                #pragma unroll
                for (int j = 0; j < 8; j++) acc[i][j] += a[i] * bb[j];
        }
        __syncthreads();
    }
    float* obase = out + (size_t)bh * 128 * 256 + blockIdx.x * 128;
    #pragma unroll
    for (int i = 0; i < 8; i++) {
        int kk = ty * 8 + i;
        #pragma unroll
        for (int j = 0; j < 8; j++)
            atomicAdd(&obase[(size_t)kk * 256 + tx * 8 + j], acc[i][j]);
    }
}

// ---------------------------------------------------------------------------
extern "C" void kernel_launch(void* const* d_in, const int* in_sizes, int n_in,
                              void* d_out, int out_size) {
    const float* seg  = (const float*)d_in[0];
    const float* nw   = (const float*)d_in[1];
    const float* Wk   = (const float*)d_in[2];
    const float* Wv   = (const float*)d_in[3];
    const float* Wg1  = (const float*)d_in[4];
    const float* Wg2  = (const float*)d_in[5];
    const float* bg2  = (const float*)d_in[6];
    const float* init = (const float*)d_in[7];
    float* out = (float*)d_out;

    k_rmsnorm<<<BT, 256>>>(seg, nw, Wg1);
    k_gate<<<32, 128>>>(Wg2, bg2);
    k_exp<<<(BT * KD) / 256, 256>>>();
    k_sgemm<0><<<dim3(KD / 128, BT / 128), 256>>>(Wk);
    k_sgemm<1><<<dim3(VD / 128, BT / 128), 256>>>(Wv);
    k_init<<<(NB * KD * 256) / 256, 256>>>(init, out);
    k_state<<<dim3(2, 32, 8), 256>>>(out);
}

// round 6
// speedup vs baseline: 1.3077x; 1.3077x over previous
#include <cuda_runtime.h>
#include <cuda_bf16.h>
#include <cstdint>

#define BT   8192
#define TT   2048
#define NB   4
#define Dm   2048
#define KD   1024
#define VD   2048

// ---------------- scratch (device globals; allocation-free rule) -----------
__device__ __align__(128) float g_x[BT * Dm];     // 64 MiB normalized input (fp32)
__device__ __align__(128) float g_k[BT * KD];     // ktilde fp32 [b][t][n]
__device__ __align__(128) float g_v[BT * VD];     // v      fp32 [b][t][n]
__device__ __align__(128) float g_e[BT * KD];     // Gcum then exp(Gtot-Gcum)
__device__ __align__(128) float g_g1[BT * 16];
__device__ __align__(128) float g_gtot[NB * KD];

// ---------------- helpers ---------------------------------------------------
__device__ __forceinline__ void mma_bf16(float* d, const uint32_t* a, uint32_t b0, uint32_t b1) {
    asm volatile("mma.sync.aligned.m16n8k16.row.col.f32.bf16.bf16.f32 "
                 "{%0,%1,%2,%3}, {%4,%5,%6,%7}, {%8,%9}, {%0,%1,%2,%3};"
                 : "+f"(d[0]), "+f"(d[1]), "+f"(d[2]), "+f"(d[3])
                 : "r"(a[0]), "r"(a[1]), "r"(a[2]), "r"(a[3]), "r"(b0), "r"(b1));
}
__device__ __forceinline__ uint32_t pack_bf2(float a, float b) {
    __nv_bfloat162 t = __floats2bfloat162_rn(a, b);  // .x=a (low), .y=b (high)
    return *(uint32_t*)&t;
}

// ---------------------------------------------------------------------------
// Kernel 1: RMSNorm (round-1 proven) -> fp32 g_x, plus g1 = x @ Wg1
// ---------------------------------------------------------------------------
__global__ __launch_bounds__(256) void k_rmsnorm(const float* __restrict__ seg,
                                                 const float* __restrict__ nw,
                                                 const float* __restrict__ Wg1) {
    int row = blockIdx.x;
    int tid = threadIdx.x;
    const float4* s4 = (const float4*)(seg + (size_t)row * Dm);
    float4 v0 = s4[tid];
    float4 v1 = s4[tid + 256];
    float ss = v0.x*v0.x + v0.y*v0.y + v0.z*v0.z + v0.w*v0.w
             + v1.x*v1.x + v1.y*v1.y + v1.z*v1.z + v1.w*v1.w;
    #pragma unroll
    for (int o = 16; o; o >>= 1) ss += __shfl_xor_sync(0xffffffffu, ss, o);
    __shared__ float sred[8];
    int wid = tid >> 5, lane = tid & 31;
    if (lane == 0) sred[wid] = ss;
    __syncthreads();
    float tot = 0.f;
    #pragma unroll
    for (int w = 0; w < 8; w++) tot += sred[w];
    float rinv = rsqrtf(tot * (1.0f / Dm) + 1e-5f);

    const float4* w4 = (const float4*)nw;
    float4 n0 = w4[tid], n1 = w4[tid + 256];
    float4 x0, x1;
    x0.x = v0.x*rinv*n0.x; x0.y = v0.y*rinv*n0.y; x0.z = v0.z*rinv*n0.z; x0.w = v0.w*rinv*n0.w;
    x1.x = v1.x*rinv*n1.x; x1.y = v1.y*rinv*n1.y; x1.z = v1.z*rinv*n1.z; x1.w = v1.w*rinv*n1.w;
    float4* xo = (float4*)(g_x + (size_t)row * Dm);
    xo[tid] = x0;
    xo[tid + 256] = x1;

    float p[16];
    #pragma unroll
    for (int j = 0; j < 16; j++) p[j] = 0.f;
    float xa[4] = {x0.x, x0.y, x0.z, x0.w};
    float xb[4] = {x1.x, x1.y, x1.z, x1.w};
    #pragma unroll
    for (int i = 0; i < 4; i++) {
        const float* wg = Wg1 + (size_t)(tid * 4 + i) * 16;
        #pragma unroll
        for (int j = 0; j < 16; j++) p[j] += xa[i] * wg[j];
    }
    #pragma unroll
    for (int i = 0; i < 4; i++) {
        const float* wg = Wg1 + (size_t)(1024 + tid * 4 + i) * 16;
        #pragma unroll
        for (int j = 0; j < 16; j++) p[j] += xb[i] * wg[j];
    }
    #pragma unroll
    for (int o = 16; o; o >>= 1) {
        #pragma unroll
        for (int j = 0; j < 16; j++) p[j] += __shfl_xor_sync(0xffffffffu, p[j], o);
    }
    __shared__ float pg[8][16];
    if (lane == 0) {
        #pragma unroll
        for (int j = 0; j < 16; j++) pg[wid][j] = p[j];
    }
    __syncthreads();
    if (tid < 16) {
        float s = 0.f;
        #pragma unroll
        for (int w = 0; w < 8; w++) s += pg[w][tid];
        g_g1[row * 16 + tid] = s;
    }
}

// ---------------------------------------------------------------------------
// Kernel 2: gate cumsum (round-1 proven): Gcum -> g_e, Gtot -> g_gtot
// ---------------------------------------------------------------------------
__global__ __launch_bounds__(128) void k_gate(const float* __restrict__ Wg2,
                                              const float* __restrict__ bg2) {
    int bh = blockIdx.x;
    int b = bh >> 3, h = bh & 7;
    int kk = threadIdx.x;
    int col = h * 128 + kk;
    float w[16];
    #pragma unroll
    for (int j = 0; j < 16; j++) w[j] = Wg2[j * KD + col];
    float bias = bg2[col];
    float cum = 0.f;
    __shared__ float sh[2048];
    const float* g1b = g_g1 + (size_t)b * TT * 16;
    float* eb = g_e + (size_t)b * TT * KD + col;
    for (int t0 = 0; t0 < TT; t0 += 128) {
        __syncthreads();
        const float4* src = (const float4*)(g1b + (size_t)t0 * 16);
        #pragma unroll
        for (int l = 0; l < 4; l++)
            ((float4*)sh)[threadIdx.x + l * 128] = src[threadIdx.x + l * 128];
        __syncthreads();
        for (int tt = 0; tt < 128; tt++) {
            float z = bias;
            #pragma unroll
            for (int j = 0; j < 16; j++) z += sh[tt * 16 + j] * w[j];
            float ls = (z >= 0.f) ? -log1pf(__expf(-z)) : (z - log1pf(__expf(z)));
            cum += ls * (1.0f / 16.0f);
            eb[(size_t)(t0 + tt) * KD] = cum;
        }
    }
    g_gtot[bh * 128 + kk] = cum;
}

// Kernel 2b (round-1 proven): e = exp(Gtot - Gcum)
__global__ __launch_bounds__(256) void k_exp() {
    size_t i = (size_t)blockIdx.x * 256 + threadIdx.x;
    int b = (int)(i >> 21);
    int col = (int)(i & 1023);
    g_e[i] = expf(g_gtot[(b << 10) | col] - g_e[i]);
}

// ---------------------------------------------------------------------------
// Kernel 3: projection GEMM via mma.sync bf16 3-term split, fp32 in/out.
// NO cp.async, NO ldmatrix. Converts fp32->bf16 hi/lo inside the kernel.
// CTA 128x128, BK=16, 8 warps (64x32 each). Register-double-buffered GMEM.
// smem: As/Bs in [row][k]-style bf16, element stride 18 (36B rows).
// ---------------------------------------------------------------------------
#define AST 18

template <int WHICH>
__global__ __launch_bounds__(256) void k_mm(const float* __restrict__ W) {
    constexpr int N = WHICH ? VD : KD;
    __shared__ __nv_bfloat16 As_h[128 * AST], As_l[128 * AST];
    __shared__ __nv_bfloat16 Bs_h[128 * AST], Bs_l[128 * AST];
    const int tid = threadIdx.x, lane = tid & 31, wid = tid >> 5;
    const int wm = wid >> 2, wn = wid & 3;
    const int n0 = blockIdx.x * 128, m0 = blockIdx.y * 128;

    const float* A = g_x + (size_t)m0 * Dm;
    const float* B = W + n0;   // W[k][n] row-major

    float acc[4][4][4];
    #pragma unroll
    for (int i = 0; i < 4; i++)
        #pragma unroll
        for (int j = 0; j < 4; j++)
            #pragma unroll
            for (int q = 0; q < 4; q++) acc[i][j][q] = 0.f;

    // global-load assignments
    const int arow = tid >> 1, ahalf = tid & 1;      // A: 128 rows x 16 k (8 fl/thr)
    const int bkk = tid >> 4, bc = (tid & 15) * 8;   // B: 16 k-rows x 128 n (8 fl/thr)
    float4 ra0, ra1, rb0, rb1;

    auto gload = [&](int k0) {
        const float4* ap = (const float4*)(A + (size_t)arow * Dm + k0 + ahalf * 8);
        ra0 = ap[0]; ra1 = ap[1];
        const float4* bp = (const float4*)(B + (size_t)(k0 + bkk) * N + bc);
        rb0 = bp[0]; rb1 = bp[1];
    };
    auto sstore = [&]() {
        // A: row arow, cols ahalf*8 .. +7
        int ab = arow * AST + ahalf * 8;
        float af[8] = {ra0.x, ra0.y, ra0.z, ra0.w, ra1.x, ra1.y, ra1.z, ra1.w};
        #pragma unroll
        for (int q = 0; q < 4; q++) {
            float f0 = af[q * 2], f1 = af[q * 2 + 1];
            float h0 = __bfloat162float(__float2bfloat16(f0));
            float h1 = __bfloat162float(__float2bfloat16(f1));
            *(uint32_t*)&As_h[ab + q * 2] = pack_bf2(f0, f1);
            *(uint32_t*)&As_l[ab + q * 2] = pack_bf2(f0 - h0, f1 - h1);
        }
        // B: k-row bkk, n-cols bc..bc+7 -> transposed store Bs[n][k]
        float bf[8] = {rb0.x, rb0.y, rb0.z, rb0.w, rb1.x, rb1.y, rb1.z, rb1.w};
        #pragma unroll
        for (int j = 0; j < 8; j++) {
            float f = bf[j];
            __nv_bfloat16 h = __float2bfloat16(f);
            Bs_h[(bc + j) * AST + bkk] = h;
            Bs_l[(bc + j) * AST + bkk] = __float2bfloat16(f - __bfloat162float(h));
        }
    };

    const int r = lane >> 2, c2 = (lane & 3) * 2;

    gload(0);
    for (int k0 = 0; k0 < Dm; k0 += 16) {
        __syncthreads();
        sstore();
        __syncthreads();
        if (k0 + 16 < Dm) gload(k0 + 16);

        uint32_t ah[4][4], al[4][4], bh[4][2], bl[4][2];
        #pragma unroll
        for (int mi = 0; mi < 4; mi++) {
            int mrow = wm * 64 + mi * 16 + r;
            ah[mi][0] = *(uint32_t*)&As_h[mrow * AST + c2];
            ah[mi][1] = *(uint32_t*)&As_h[(mrow + 8) * AST + c2];
            ah[mi][2] = *(uint32_t*)&As_h[mrow * AST + c2 + 8];
            ah[mi][3] = *(uint32_t*)&As_h[(mrow + 8) * AST + c2 + 8];
            al[mi][0] = *(uint32_t*)&As_l[mrow * AST + c2];
            al[mi][1] = *(uint32_t*)&As_l[(mrow + 8) * AST + c2];
            al[mi][2] = *(uint32_t*)&As_l[mrow * AST + c2 + 8];
            al[mi][3] = *(uint32_t*)&As_l[(mrow + 8) * AST + c2 + 8];
        }
        #pragma unroll
        for (int nj = 0; nj < 4; nj++) {
            int nrow = wn * 32 + nj * 8 + r;
            bh[nj][0] = *(uint32_t*)&Bs_h[nrow * AST + c2];
            bh[nj][1] = *(uint32_t*)&Bs_h[nrow * AST + c2 + 8];
            bl[nj][0] = *(uint32_t*)&Bs_l[nrow * AST + c2];
            bl[nj][1] = *(uint32_t*)&Bs_l[nrow * AST + c2 + 8];
        }
        #pragma unroll
        for (int mi = 0; mi < 4; mi++)
            #pragma unroll
            for (int nj = 0; nj < 4; nj++) {
                mma_bf16(acc[mi][nj], ah[mi], bh[nj][0], bh[nj][1]);
                mma_bf16(acc[mi][nj], ah[mi], bl[nj][0], bl[nj][1]);
                mma_bf16(acc[mi][nj], al[mi], bh[nj][0], bh[nj][1]);
            }
    }

    float* C = WHICH ? g_v : g_k;
    #pragma unroll
    for (int mi = 0; mi < 4; mi++) {
        int m_ = m0 + wm * 64 + mi * 16 + r;
        #pragma unroll
        for (int nj = 0; nj < 4; nj++) {
            int n_ = n0 + wn * 32 + nj * 8 + c2;
            float v0 = acc[mi][nj][0], v1 = acc[mi][nj][1];
            float v2 = acc[mi][nj][2], v3 = acc[mi][nj][3];
            if (WHICH == 0) {
                float2 e0 = *(const float2*)&g_e[(size_t)m_ * KD + n_];
                float2 e1 = *(const float2*)&g_e[(size_t)(m_ + 8) * KD + n_];
                v0 *= e0.x; v1 *= e0.y; v2 *= e1.x; v3 *= e1.y;
            }
            *(float2*)&C[(size_t)m_ * N + n_]       = make_float2(v0, v1);
            *(float2*)&C[(size_t)(m_ + 8) * N + n_] = make_float2(v2, v3);
        }
    }
}

// ---------------------------------------------------------------------------
// Kernel 4a (round-1 proven): out = initial_state * exp(Gtot)
// ---------------------------------------------------------------------------
__global__ __launch_bounds__(256) void k_init(const float* __restrict__ init,
                                              float* __restrict__ out) {
    int i = blockIdx.x * 256 + threadIdx.x;
    out[i] = init[i] * expf(g_gtot[i >> 8]);
}

// ---------------------------------------------------------------------------
// Kernel 4b (round-1 proven): S[bh] += ktilde^T @ v ; split-K atomics
// ---------------------------------------------------------------------------
__global__ __launch_bounds__(256) void k_state(float* __restrict__ out) {
    int bh = blockIdx.y;
    int b = bh >> 3, h = bh & 7;
    int tseg0 = blockIdx.z * 256;
    __shared__ __align__(16) float As[16][128];
    __shared__ __align__(16) float Bs[16][128];
    const float* Abase = g_k + (size_t)b * TT * KD + h * 128;
    const float* Bbase = g_v + (size_t)b * TT * VD + h * 256 + blockIdx.x * 128;
    int tid = threadIdx.x;
    int tx = tid & 15, ty = tid >> 4;
    float acc[8][8];
    #pragma unroll
    for (int i = 0; i < 8; i++)
        #pragma unroll
        for (int j = 0; j < 8; j++) acc[i][j] = 0.f;

    for (int t0 = tseg0; t0 < tseg0 + 256; t0 += 16) {
        #pragma unroll
        for (int l = 0; l < 2; l++) {
            int f = tid + l * 256;
            int rr = f >> 5, cc = (f & 31) * 4;
            *(float4*)&As[rr][cc] = *(const float4*)(Abase + (size_t)(t0 + rr) * KD + cc);
            *(float4*)&Bs[rr][cc] = *(const float4*)(Bbase + (size_t)(t0 + rr) * VD + cc);
        }
        __syncthreads();
        #pragma unroll
        for (int tt = 0; tt < 16; tt++) {
            float4 a0 = *(const float4*)&As[tt][ty * 8];
            float4 a1 = *(const float4*)&As[tt][ty * 8 + 4];
            float4 b0 = *(const float4*)&Bs[tt][tx * 8];
            float4 b1 = *(const float4*)&Bs[tt][tx * 8 + 4];
            float a[8] = {a0.x, a0.y, a0.z, a0.w, a1.x, a1.y, a1.z, a1.w};
            float bb[8] = {b0.x, b0.y, b0.z, b0.w, b1.x, b1.y, b1.z, b1.w};
            #pragma unroll
            for (int i = 0; i < 8; i++)
                #pragma unroll
                for (int j = 0; j < 8; j++) acc[i][j] += a[i] * bb[j];
        }
        __syncthreads();
    }
    float* obase = out + (size_t)bh * 128 * 256 + blockIdx.x * 128;
    #pragma unroll
    for (int i = 0; i < 8; i++) {
        int kk = ty * 8 + i;
        #pragma unroll
        for (int j = 0; j < 8; j++)
            atomicAdd(&obase[(size_t)kk * 256 + tx * 8 + j], acc[i][j]);
    }
}

// ---------------------------------------------------------------------------
extern "C" void kernel_launch(void* const* d_in, const int* in_sizes, int n_in,
                              void* d_out, int out_size) {
    const float* seg  = (const float*)d_in[0];
    const float* nw   = (const float*)d_in[1];
    const float* Wk   = (const float*)d_in[2];
    const float* Wv   = (const float*)d_in[3];
    const float* Wg1  = (const float*)d_in[4];
    const float* Wg2  = (const float*)d_in[5];
    const float* bg2  = (const float*)d_in[6];
    const float* init = (const float*)d_in[7];
    float* out = (float*)d_out;

    k_rmsnorm<<<BT, 256>>>(seg, nw, Wg1);
    k_gate<<<32, 128>>>(Wg2, bg2);
    k_exp<<<(BT * KD) / 256, 256>>>();
    k_mm<0><<<dim3(KD / 128, BT / 128), 256>>>(Wk);
    k_mm<1><<<dim3(VD / 128, BT / 128), 256>>>(Wv);
    k_init<<<(NB * KD * 256) / 256, 256>>>(init, out);
    k_state<<<dim3(2, 32, 8), 256>>>(out);
}

// round 7
// speedup vs baseline: 1.4181x; 1.0844x over previous
#include <cuda_runtime.h>
#include <cuda_bf16.h>
#include <cstdint>

#define BT   8192
#define TT   2048
#define NB   4
#define Dm   2048
#define KD   1024
#define VD   2048

// ---------------- scratch (device globals; allocation-free rule) -----------
__device__ __align__(128) float g_x[BT * Dm];     // normalized input (fp32)
__device__ __align__(128) float g_k[BT * KD];     // ktilde fp32 [b][t][n]
__device__ __align__(128) float g_v[BT * VD];     // v      fp32 [b][t][n]
__device__ __align__(128) float g_e[BT * KD];     // Gcum (inclusive cumsum of ls)
__device__ __align__(128) float g_g1[BT * 16];
__device__ __align__(128) float g_gtot[NB * KD];

// ---------------- helpers ---------------------------------------------------
__device__ __forceinline__ uint32_t smem_u32(const void* p) {
    uint32_t a;
    asm("{ .reg .u64 t; cvta.to.shared.u64 t, %1; cvt.u32.u64 %0, t; }" : "=r"(a) : "l"(p));
    return a;
}
__device__ __forceinline__ void mma_bf16(float* d, const uint32_t* a, uint32_t b0, uint32_t b1) {
    asm volatile("mma.sync.aligned.m16n8k16.row.col.f32.bf16.bf16.f32 "
                 "{%0,%1,%2,%3}, {%4,%5,%6,%7}, {%8,%9}, {%0,%1,%2,%3};"
                 : "+f"(d[0]), "+f"(d[1]), "+f"(d[2]), "+f"(d[3])
                 : "r"(a[0]), "r"(a[1]), "r"(a[2]), "r"(a[3]), "r"(b0), "r"(b1));
}
#define LDSM4(r, a) \
    asm volatile("ldmatrix.sync.aligned.m8n8.x4.shared.b16 {%0,%1,%2,%3}, [%4];" \
        : "=r"((r)[0]), "=r"((r)[1]), "=r"((r)[2]), "=r"((r)[3]) : "r"(a))
#define LDSM4T(r, a) \
    asm volatile("ldmatrix.sync.aligned.m8n8.x4.trans.shared.b16 {%0,%1,%2,%3}, [%4];" \
        : "=r"((r)[0]), "=r"((r)[1]), "=r"((r)[2]), "=r"((r)[3]) : "r"(a))
__device__ __forceinline__ uint32_t pack_bf2(float a, float b) {
    __nv_bfloat162 t = __floats2bfloat162_rn(a, b);
    return *(uint32_t*)&t;
}

// ---------------------------------------------------------------------------
// Kernel 1: RMSNorm (proven) -> fp32 g_x, plus g1 = x @ Wg1
// ---------------------------------------------------------------------------
__global__ __launch_bounds__(256) void k_rmsnorm(const float* __restrict__ seg,
                                                 const float* __restrict__ nw,
                                                 const float* __restrict__ Wg1) {
    int row = blockIdx.x;
    int tid = threadIdx.x;
    const float4* s4 = (const float4*)(seg + (size_t)row * Dm);
    float4 v0 = s4[tid];
    float4 v1 = s4[tid + 256];
    float ss = v0.x*v0.x + v0.y*v0.y + v0.z*v0.z + v0.w*v0.w
             + v1.x*v1.x + v1.y*v1.y + v1.z*v1.z + v1.w*v1.w;
    #pragma unroll
    for (int o = 16; o; o >>= 1) ss += __shfl_xor_sync(0xffffffffu, ss, o);
    __shared__ float sred[8];
    int wid = tid >> 5, lane = tid & 31;
    if (lane == 0) sred[wid] = ss;
    __syncthreads();
    float tot = 0.f;
    #pragma unroll
    for (int w = 0; w < 8; w++) tot += sred[w];
    float rinv = rsqrtf(tot * (1.0f / Dm) + 1e-5f);

    const float4* w4 = (const float4*)nw;
    float4 n0 = w4[tid], n1 = w4[tid + 256];
    float4 x0, x1;
    x0.x = v0.x*rinv*n0.x; x0.y = v0.y*rinv*n0.y; x0.z = v0.z*rinv*n0.z; x0.w = v0.w*rinv*n0.w;
    x1.x = v1.x*rinv*n1.x; x1.y = v1.y*rinv*n1.y; x1.z = v1.z*rinv*n1.z; x1.w = v1.w*rinv*n1.w;
    float4* xo = (float4*)(g_x + (size_t)row * Dm);
    xo[tid] = x0;
    xo[tid + 256] = x1;

    float p[16];
    #pragma unroll
    for (int j = 0; j < 16; j++) p[j] = 0.f;
    float xa[4] = {x0.x, x0.y, x0.z, x0.w};
    float xb[4] = {x1.x, x1.y, x1.z, x1.w};
    #pragma unroll
    for (int i = 0; i < 4; i++) {
        const float* wg = Wg1 + (size_t)(tid * 4 + i) * 16;
        #pragma unroll
        for (int j = 0; j < 16; j++) p[j] += xa[i] * wg[j];
    }
    #pragma unroll
    for (int i = 0; i < 4; i++) {
        const float* wg = Wg1 + (size_t)(1024 + tid * 4 + i) * 16;
        #pragma unroll
        for (int j = 0; j < 16; j++) p[j] += xb[i] * wg[j];
    }
    #pragma unroll
    for (int o = 16; o; o >>= 1) {
        #pragma unroll
        for (int j = 0; j < 16; j++) p[j] += __shfl_xor_sync(0xffffffffu, p[j], o);
    }
    __shared__ float pg[8][16];
    if (lane == 0) {
        #pragma unroll
        for (int j = 0; j < 16; j++) pg[wid][j] = p[j];
    }
    __syncthreads();
    if (tid < 16) {
        float s = 0.f;
        #pragma unroll
        for (int w = 0; w < 8; w++) s += pg[w][tid];
        g_g1[row * 16 + tid] = s;
    }
}

// ---------------------------------------------------------------------------
// Kernel 2 (proven): gate cumsum: Gcum -> g_e, Gtot -> g_gtot
// ---------------------------------------------------------------------------
__global__ __launch_bounds__(128) void k_gate(const float* __restrict__ Wg2,
                                              const float* __restrict__ bg2) {
    int bh = blockIdx.x;
    int b = bh >> 3, h = bh & 7;
    int kk = threadIdx.x;
    int col = h * 128 + kk;
    float w[16];
    #pragma unroll
    for (int j = 0; j < 16; j++) w[j] = Wg2[j * KD + col];
    float bias = bg2[col];
    float cum = 0.f;
    __shared__ float sh[2048];
    const float* g1b = g_g1 + (size_t)b * TT * 16;
    float* eb = g_e + (size_t)b * TT * KD + col;
    for (int t0 = 0; t0 < TT; t0 += 128) {
        __syncthreads();
        const float4* src = (const float4*)(g1b + (size_t)t0 * 16);
        #pragma unroll
        for (int l = 0; l < 4; l++)
            ((float4*)sh)[threadIdx.x + l * 128] = src[threadIdx.x + l * 128];
        __syncthreads();
        for (int tt = 0; tt < 128; tt++) {
            float z = bias;
            #pragma unroll
            for (int j = 0; j < 16; j++) z += sh[tt * 16 + j] * w[j];
            float ls = (z >= 0.f) ? -log1pf(__expf(-z)) : (z - log1pf(__expf(z)));
            cum += ls * (1.0f / 16.0f);
            eb[(size_t)(t0 + tt) * KD] = cum;
        }
    }
    g_gtot[bh * 128 + kk] = cum;
}

// ---------------------------------------------------------------------------
// Kernel 3: projection GEMM, mma.sync bf16 3-term split, ldmatrix fragments.
// CTA 128x128, BK=32, 8 warps (64x32). In-kernel fp32->bf16 hi/lo split.
// A smem [m][k]: 80B rows (conflict-free). B smem [k][n]: 272B rows, ldmatrix.trans.
// WHICH==0 epilogue applies e = exp(gtot - Gcum) (fused k_exp).
// ---------------------------------------------------------------------------
#define A_ST 40    // bf16 elems per A row (80B)
#define B_ST 136   // bf16 elems per B row (272B)

template <int WHICH>
__global__ __launch_bounds__(256) void k_mm(const float* __restrict__ W) {
    constexpr int N = WHICH ? VD : KD;
    __shared__ __align__(16) __nv_bfloat16 As_h[128 * A_ST], As_l[128 * A_ST];
    __shared__ __align__(16) __nv_bfloat16 Bs_h[32 * B_ST],  Bs_l[32 * B_ST];
    const int tid = threadIdx.x, lane = tid & 31, wid = tid >> 5;
    const int wm = wid >> 2, wn = wid & 3;
    const int n0 = blockIdx.x * 128, m0 = blockIdx.y * 128;

    const float* A = g_x + (size_t)m0 * Dm;
    const float* B = W + n0;

    const uint32_t ash = smem_u32(As_h), asl = smem_u32(As_l);
    const uint32_t bsh = smem_u32(Bs_h), bsl = smem_u32(Bs_l);

    float acc[4][4][4];
    #pragma unroll
    for (int i = 0; i < 4; i++)
        #pragma unroll
        for (int j = 0; j < 4; j++)
            #pragma unroll
            for (int q = 0; q < 4; q++) acc[i][j][q] = 0.f;

    const int arow = tid >> 1, ahalf = (tid & 1) * 16;
    const int brow = tid >> 3, bcol = (tid & 7) * 16;
    float4 ra[4], rb[4];

    auto gload = [&](int k0) {
        const float4* ap = (const float4*)(A + (size_t)arow * Dm + k0 + ahalf);
        #pragma unroll
        for (int q = 0; q < 4; q++) ra[q] = ap[q];
        const float4* bp = (const float4*)(B + (size_t)(k0 + brow) * N + bcol);
        #pragma unroll
        for (int q = 0; q < 4; q++) rb[q] = bp[q];
    };
    auto sstore = [&]() {
        int ab = arow * A_ST + ahalf;
        #pragma unroll
        for (int q = 0; q < 4; q++) {
            float f0 = ra[q].x, f1 = ra[q].y, f2 = ra[q].z, f3 = ra[q].w;
            uint32_t h01 = pack_bf2(f0, f1), h23 = pack_bf2(f2, f3);
            float r0 = f0 - __bfloat162float(__float2bfloat16(f0));
            float r1 = f1 - __bfloat162float(__float2bfloat16(f1));
            float r2 = f2 - __bfloat162float(__float2bfloat16(f2));
            float r3 = f3 - __bfloat162float(__float2bfloat16(f3));
            *(uint2*)&As_h[ab + q * 4] = make_uint2(h01, h23);
            *(uint2*)&As_l[ab + q * 4] = make_uint2(pack_bf2(r0, r1), pack_bf2(r2, r3));
        }
        int bb = brow * B_ST + bcol;
        #pragma unroll
        for (int q = 0; q < 4; q++) {
            float f0 = rb[q].x, f1 = rb[q].y, f2 = rb[q].z, f3 = rb[q].w;
            uint32_t h01 = pack_bf2(f0, f1), h23 = pack_bf2(f2, f3);
            float r0 = f0 - __bfloat162float(__float2bfloat16(f0));
            float r1 = f1 - __bfloat162float(__float2bfloat16(f1));
            float r2 = f2 - __bfloat162float(__float2bfloat16(f2));
            float r3 = f3 - __bfloat162float(__float2bfloat16(f3));
            *(uint2*)&Bs_h[bb + q * 4] = make_uint2(h01, h23);
            *(uint2*)&Bs_l[bb + q * 4] = make_uint2(pack_bf2(r0, r1), pack_bf2(r2, r3));
        }
    };

    gload(0);
    for (int k0 = 0; k0 < Dm; k0 += 32) {
        __syncthreads();
        sstore();
        __syncthreads();
        if (k0 + 32 < Dm) gload(k0 + 32);

        #pragma unroll
        for (int kg = 0; kg < 2; kg++) {
            uint32_t ah[4][4], al[4][4], bh[2][4], bl[2][4];
            #pragma unroll
            for (int mi = 0; mi < 4; mi++) {
                uint32_t off = ((wm * 64 + mi * 16 + (lane & 15)) * A_ST + kg * 16) * 2
                             + (lane >> 4) * 16;
                LDSM4(ah[mi], ash + off);
                LDSM4(al[mi], asl + off);
            }
            #pragma unroll
            for (int nh = 0; nh < 2; nh++) {
                uint32_t off = ((kg * 16 + (lane & 15)) * B_ST + wn * 32 + nh * 16) * 2
                             + (lane >> 4) * 16;
                LDSM4T(bh[nh], bsh + off);
                LDSM4T(bl[nh], bsl + off);
            }
            #pragma unroll
            for (int mi = 0; mi < 4; mi++)
                #pragma unroll
                for (int nj = 0; nj < 4; nj++) {
                    int nh = nj >> 1, oc = (nj & 1) * 2;
                    mma_bf16(acc[mi][nj], ah[mi], bh[nh][oc], bh[nh][oc + 1]);
                    mma_bf16(acc[mi][nj], ah[mi], bl[nh][oc], bl[nh][oc + 1]);
                    mma_bf16(acc[mi][nj], al[mi], bh[nh][oc], bh[nh][oc + 1]);
                }
        }
    }

    const int r = lane >> 2, c2 = (lane & 3) * 2;
    float* C = WHICH ? g_v : g_k;
    #pragma unroll
    for (int mi = 0; mi < 4; mi++) {
        int m_ = m0 + wm * 64 + mi * 16 + r;
        #pragma unroll
        for (int nj = 0; nj < 4; nj++) {
            int n_ = n0 + wn * 32 + nj * 8 + c2;
            float v0 = acc[mi][nj][0], v1 = acc[mi][nj][1];
            float v2 = acc[mi][nj][2], v3 = acc[mi][nj][3];
            if (WHICH == 0) {
                int bi = m_ >> 11;
                float gt0 = g_gtot[(bi << 10) | n_];
                float gt1 = g_gtot[(bi << 10) | (n_ + 1)];
                float2 c0 = *(const float2*)&g_e[(size_t)m_ * KD + n_];
                float2 c1 = *(const float2*)&g_e[(size_t)(m_ + 8) * KD + n_];
                v0 *= expf(gt0 - c0.x); v1 *= expf(gt1 - c0.y);
                v2 *= expf(gt0 - c1.x); v3 *= expf(gt1 - c1.y);
            }
            *(float2*)&C[(size_t)m_ * N + n_]       = make_float2(v0, v1);
            *(float2*)&C[(size_t)(m_ + 8) * N + n_] = make_float2(v2, v3);
        }
    }
}

// ---------------------------------------------------------------------------
// Kernel 4a (proven): out = initial_state * exp(Gtot)
// ---------------------------------------------------------------------------
__global__ __launch_bounds__(256) void k_init(const float* __restrict__ init,
                                              float* __restrict__ out) {
    int i = blockIdx.x * 256 + threadIdx.x;
    out[i] = init[i] * expf(g_gtot[i >> 8]);
}

// ---------------------------------------------------------------------------
// Kernel 4b (proven): S[bh] += ktilde^T @ v ; split-K atomics (fp32)
// ---------------------------------------------------------------------------
__global__ __launch_bounds__(256) void k_state(float* __restrict__ out) {
    int bh = blockIdx.y;
    int b = bh >> 3, h = bh & 7;
    int tseg0 = blockIdx.z * 256;
    __shared__ __align__(16) float As[16][128];
    __shared__ __align__(16) float Bs[16][128];
    const float* Abase = g_k + (size_t)b * TT * KD + h * 128;
    const float* Bbase = g_v + (size_t)b * TT * VD + h * 256 + blockIdx.x * 128;
    int tid = threadIdx.x;
    int tx = tid & 15, ty = tid >> 4;
    float acc[8][8];
    #pragma unroll
    for (int i = 0; i < 8; i++)
        #pragma unroll
        for (int j = 0; j < 8; j++) acc[i][j] = 0.f;

    for (int t0 = tseg0; t0 < tseg0 + 256; t0 += 16) {
        #pragma unroll
        for (int l = 0; l < 2; l++) {
            int f = tid + l * 256;
            int rr = f >> 5, cc = (f & 31) * 4;
            *(float4*)&As[rr][cc] = *(const float4*)(Abase + (size_t)(t0 + rr) * KD + cc);
            *(float4*)&Bs[rr][cc] = *(const float4*)(Bbase + (size_t)(t0 + rr) * VD + cc);
        }
        __syncthreads();
        #pragma unroll
        for (int tt = 0; tt < 16; tt++) {
            float4 a0 = *(const float4*)&As[tt][ty * 8];
            float4 a1 = *(const float4*)&As[tt][ty * 8 + 4];
            float4 b0 = *(const float4*)&Bs[tt][tx * 8];
            float4 b1 = *(const float4*)&Bs[tt][tx * 8 + 4];
            float a[8] = {a0.x, a0.y, a0.z, a0.w, a1.x, a1.y, a1.z, a1.w};
            float bb[8] = {b0.x, b0.y, b0.z, b0.w, b1.x, b1.y, b1.z, b1.w};
            #pragma unroll
            for (int i = 0; i < 8; i++)
                #pragma unroll
                for (int j = 0; j < 8; j++) acc[i][j] += a[i] * bb[j];
        }
        __syncthreads();
    }
    float* obase = out + (size_t)bh * 128 * 256 + blockIdx.x * 128;
    #pragma unroll
    for (int i = 0; i < 8; i++) {
        int kk = ty * 8 + i;
        #pragma unroll
        for (int j = 0; j < 8; j++)
            atomicAdd(&obase[(size_t)kk * 256 + tx * 8 + j], acc[i][j]);
    }
}

// ---------------------------------------------------------------------------
extern "C" void kernel_launch(void* const* d_in, const int* in_sizes, int n_in,
                              void* d_out, int out_size) {
    const float* seg  = (const float*)d_in[0];
    const float* nw   = (const float*)d_in[1];
    const float* Wk   = (const float*)d_in[2];
    const float* Wv   = (const float*)d_in[3];
    const float* Wg1  = (const float*)d_in[4];
    const float* Wg2  = (const float*)d_in[5];
    const float* bg2  = (const float*)d_in[6];
    const float* init = (const float*)d_in[7];
    float* out = (float*)d_out;

    k_rmsnorm<<<BT, 256>>>(seg, nw, Wg1);
    k_gate<<<32, 128>>>(Wg2, bg2);
    k_mm<0><<<dim3(KD / 128, BT / 128), 256>>>(Wk);
    k_mm<1><<<dim3(VD / 128, BT / 128), 256>>>(Wv);
    k_init<<<(NB * KD * 256) / 256, 256>>>(init, out);
    k_state<<<dim3(2, 32, 8), 256>>>(out);
}

// round 8
// speedup vs baseline: 1.9635x; 1.3846x over previous
#include <cuda_runtime.h>
#include <cuda_bf16.h>
#include <cstdint>

#define BT   8192
#define TT   2048
#define NB   4
#define Dm   2048
#define KD   1024
#define VD   2048

// ---------------- scratch (device globals; allocation-free rule) -----------
__device__ __align__(128) float g_x[BT * Dm];     // normalized input (fp32)
__device__ __align__(128) float g_k[BT * KD];     // ktilde fp32 [b][t][n]
__device__ __align__(128) float g_v[BT * VD];     // v      fp32 [b][t][n]
__device__ __align__(128) float g_e[BT * KD];     // ls, then e = exp(Gtot-Gcum)
__device__ __align__(128) float g_g1[BT * 16];
__device__ __align__(128) float g_csum[NB * KD * 32];
__device__ __align__(128) float g_gtot[NB * KD];

// ---------------- helpers ---------------------------------------------------
__device__ __forceinline__ uint32_t smem_u32(const void* p) {
    uint32_t a;
    asm("{ .reg .u64 t; cvta.to.shared.u64 t, %1; cvt.u32.u64 %0, t; }" : "=r"(a) : "l"(p));
    return a;
}
__device__ __forceinline__ void mma_bf16(float* d, const uint32_t* a, uint32_t b0, uint32_t b1) {
    asm volatile("mma.sync.aligned.m16n8k16.row.col.f32.bf16.bf16.f32 "
                 "{%0,%1,%2,%3}, {%4,%5,%6,%7}, {%8,%9}, {%0,%1,%2,%3};"
                 : "+f"(d[0]), "+f"(d[1]), "+f"(d[2]), "+f"(d[3])
                 : "r"(a[0]), "r"(a[1]), "r"(a[2]), "r"(a[3]), "r"(b0), "r"(b1));
}
#define LDSM4(r, a) \
    asm volatile("ldmatrix.sync.aligned.m8n8.x4.shared.b16 {%0,%1,%2,%3}, [%4];" \
        : "=r"((r)[0]), "=r"((r)[1]), "=r"((r)[2]), "=r"((r)[3]) : "r"(a))
#define LDSM4T(r, a) \
    asm volatile("ldmatrix.sync.aligned.m8n8.x4.trans.shared.b16 {%0,%1,%2,%3}, [%4];" \
        : "=r"((r)[0]), "=r"((r)[1]), "=r"((r)[2]), "=r"((r)[3]) : "r"(a))
__device__ __forceinline__ uint32_t pack_bf2(float a, float b) {
    __nv_bfloat162 t = __floats2bfloat162_rn(a, b);
    return *(uint32_t*)&t;
}

// ---------------------------------------------------------------------------
// Kernel 1: RMSNorm (proven) -> fp32 g_x, plus g1 = x @ Wg1
// ---------------------------------------------------------------------------
__global__ __launch_bounds__(256) void k_rmsnorm(const float* __restrict__ seg,
                                                 const float* __restrict__ nw,
                                                 const float* __restrict__ Wg1) {
    int row = blockIdx.x;
    int tid = threadIdx.x;
    const float4* s4 = (const float4*)(seg + (size_t)row * Dm);
    float4 v0 = s4[tid];
    float4 v1 = s4[tid + 256];
    float ss = v0.x*v0.x + v0.y*v0.y + v0.z*v0.z + v0.w*v0.w
             + v1.x*v1.x + v1.y*v1.y + v1.z*v1.z + v1.w*v1.w;
    #pragma unroll
    for (int o = 16; o; o >>= 1) ss += __shfl_xor_sync(0xffffffffu, ss, o);
    __shared__ float sred[8];
    int wid = tid >> 5, lane = tid & 31;
    if (lane == 0) sred[wid] = ss;
    __syncthreads();
    float tot = 0.f;
    #pragma unroll
    for (int w = 0; w < 8; w++) tot += sred[w];
    float rinv = rsqrtf(tot * (1.0f / Dm) + 1e-5f);

    const float4* w4 = (const float4*)nw;
    float4 n0 = w4[tid], n1 = w4[tid + 256];
    float4 x0, x1;
    x0.x = v0.x*rinv*n0.x; x0.y = v0.y*rinv*n0.y; x0.z = v0.z*rinv*n0.z; x0.w = v0.w*rinv*n0.w;
    x1.x = v1.x*rinv*n1.x; x1.y = v1.y*rinv*n1.y; x1.z = v1.z*rinv*n1.z; x1.w = v1.w*rinv*n1.w;
    float4* xo = (float4*)(g_x + (size_t)row * Dm);
    xo[tid] = x0;
    xo[tid + 256] = x1;

    float p[16];
    #pragma unroll
    for (int j = 0; j < 16; j++) p[j] = 0.f;
    float xa[4] = {x0.x, x0.y, x0.z, x0.w};
    float xb[4] = {x1.x, x1.y, x1.z, x1.w};
    #pragma unroll
    for (int i = 0; i < 4; i++) {
        const float* wg = Wg1 + (size_t)(tid * 4 + i) * 16;
        #pragma unroll
        for (int j = 0; j < 16; j++) p[j] += xa[i] * wg[j];
    }
    #pragma unroll
    for (int i = 0; i < 4; i++) {
        const float* wg = Wg1 + (size_t)(1024 + tid * 4 + i) * 16;
        #pragma unroll
        for (int j = 0; j < 16; j++) p[j] += xb[i] * wg[j];
    }
    #pragma unroll
    for (int o = 16; o; o >>= 1) {
        #pragma unroll
        for (int j = 0; j < 16; j++) p[j] += __shfl_xor_sync(0xffffffffu, p[j], o);
    }
    __shared__ float pg[8][16];
    if (lane == 0) {
        #pragma unroll
        for (int j = 0; j < 16; j++) pg[wid][j] = p[j];
    }
    __syncthreads();
    if (tid < 16) {
        float s = 0.f;
        #pragma unroll
        for (int w = 0; w < 8; w++) s += pg[w][tid];
        g_g1[row * 16 + tid] = s;
    }
}

// ---------------------------------------------------------------------------
// Gate phase 1: ls = log_sigmoid(g1@Wg2+b)/16 -> g_e; chunk sums -> g_csum
// ---------------------------------------------------------------------------
__global__ __launch_bounds__(256) void k_gate1(const float* __restrict__ Wg2,
                                               const float* __restrict__ bg2) {
    int blk = blockIdx.x;
    int b = blk >> 5, tc = blk & 31, t0 = tc * 64;
    int tid = threadIdx.x;
    __shared__ float sh[64 * 16];
    ((float4*)sh)[tid] = ((const float4*)(g_g1 + ((size_t)b * TT + t0) * 16))[tid];
    __syncthreads();
    float w[4][16], bias[4], cs[4] = {0.f, 0.f, 0.f, 0.f};
    #pragma unroll
    for (int cc = 0; cc < 4; cc++) {
        int col = cc * 256 + tid;
        #pragma unroll
        for (int j = 0; j < 16; j++) w[cc][j] = Wg2[j * KD + col];
        bias[cc] = bg2[col];
    }
    for (int t = 0; t < 64; t++) {
        const float* g1r = sh + t * 16;
        float* er = g_e + ((size_t)b * TT + t0 + t) * KD;
        #pragma unroll
        for (int cc = 0; cc < 4; cc++) {
            float z = bias[cc];
            #pragma unroll
            for (int j = 0; j < 16; j++) z += g1r[j] * w[cc][j];
            float ls = (fminf(z, 0.f) - log1pf(__expf(-fabsf(z)))) * 0.0625f;
            cs[cc] += ls;
            er[cc * 256 + tid] = ls;
        }
    }
    #pragma unroll
    for (int cc = 0; cc < 4; cc++)
        g_csum[((size_t)b * KD + cc * 256 + tid) * 32 + tc] = cs[cc];
}

// Gate phase 2: totals -> g_gtot
__global__ __launch_bounds__(256) void k_gate2() {
    int i = blockIdx.x * 256 + threadIdx.x;   // 4096 = NB*KD
    float s = 0.f;
    #pragma unroll
    for (int j = 0; j < 32; j++) s += g_csum[(size_t)i * 32 + j];
    g_gtot[i] = s;
}

// Gate phase 3: in-place e = exp(suffix-sum of ls)  [e(t) = exp(sum_{s>t} ls)]
__global__ __launch_bounds__(256) void k_gate3() {
    int blk = blockIdx.x;
    int b = blk >> 5, tc = blk & 31, t0 = tc * 64;
    int tid = threadIdx.x;
    float suf[4];
    #pragma unroll
    for (int cc = 0; cc < 4; cc++) {
        int col = cc * 256 + tid;
        const float* cp = &g_csum[((size_t)b * KD + col) * 32];
        float s = 0.f;
        for (int j = tc + 1; j < 32; j++) s += cp[j];
        suf[cc] = s;
    }
    for (int t = 63; t >= 0; t--) {
        float* er = g_e + ((size_t)b * TT + t0 + t) * KD;
        #pragma unroll
        for (int cc = 0; cc < 4; cc++) {
            float ls = er[cc * 256 + tid];
            er[cc * 256 + tid] = expf(suf[cc]);
            suf[cc] += ls;
        }
    }
}

// ---------------------------------------------------------------------------
// Kernel 3: projection GEMM, mma.sync bf16 3-term split, ldmatrix fragments.
// CTA 128x128, BK=16, 8 warps (64x32), 2 CTAs/SM (launch_bounds 256,2).
// A smem [m][k]: 48B stride (12 words == 4 mod 32 -> ldmatrix conflict-free).
// B smem [k][n]: 272B stride (68 words == 4 mod 32 -> trans conflict-free).
// WHICH==0 epilogue multiplies by precomputed g_e.
// ---------------------------------------------------------------------------
#define A_ST 24    // bf16 elems per A row (48B)
#define B_ST 136   // bf16 elems per B row (272B)

template <int WHICH>
__global__ __launch_bounds__(256, 2) void k_mm(const float* __restrict__ W) {
    constexpr int N = WHICH ? VD : KD;
    __shared__ __align__(16) __nv_bfloat16 As_h[128 * A_ST], As_l[128 * A_ST];
    __shared__ __align__(16) __nv_bfloat16 Bs_h[16 * B_ST],  Bs_l[16 * B_ST];
    const int tid = threadIdx.x, lane = tid & 31, wid = tid >> 5;
    const int wm = wid >> 2, wn = wid & 3;
    const int n0 = blockIdx.x * 128, m0 = blockIdx.y * 128;

    const float* A = g_x + (size_t)m0 * Dm;
    const float* B = W + n0;

    const uint32_t ash = smem_u32(As_h), asl = smem_u32(As_l);
    const uint32_t bsh = smem_u32(Bs_h), bsl = smem_u32(Bs_l);

    float acc[4][4][4];
    #pragma unroll
    for (int i = 0; i < 4; i++)
        #pragma unroll
        for (int j = 0; j < 4; j++)
            #pragma unroll
            for (int q = 0; q < 4; q++) acc[i][j][q] = 0.f;

    const int arow = tid >> 1, ahalf = (tid & 1) * 8;   // A: 128r x 16k, 8 f32/thr
    const int brow = tid >> 4, bcol = (tid & 15) * 8;   // B: 16r x 128n, 8 f32/thr
    float4 ra[2], rb[2];

    auto gload = [&](int k0) {
        const float4* ap = (const float4*)(A + (size_t)arow * Dm + k0 + ahalf);
        ra[0] = ap[0]; ra[1] = ap[1];
        const float4* bp = (const float4*)(B + (size_t)(k0 + brow) * N + bcol);
        rb[0] = bp[0]; rb[1] = bp[1];
    };
    auto sstore = [&]() {
        int ab = arow * A_ST + ahalf;
        #pragma unroll
        for (int q = 0; q < 2; q++) {
            float f0 = ra[q].x, f1 = ra[q].y, f2 = ra[q].z, f3 = ra[q].w;
            float r0 = f0 - __bfloat162float(__float2bfloat16(f0));
            float r1 = f1 - __bfloat162float(__float2bfloat16(f1));
            float r2 = f2 - __bfloat162float(__float2bfloat16(f2));
            float r3 = f3 - __bfloat162float(__float2bfloat16(f3));
            *(uint2*)&As_h[ab + q * 4] = make_uint2(pack_bf2(f0, f1), pack_bf2(f2, f3));
            *(uint2*)&As_l[ab + q * 4] = make_uint2(pack_bf2(r0, r1), pack_bf2(r2, r3));
        }
        int bb = brow * B_ST + bcol;
        #pragma unroll
        for (int q = 0; q < 2; q++) {
            float f0 = rb[q].x, f1 = rb[q].y, f2 = rb[q].z, f3 = rb[q].w;
            float r0 = f0 - __bfloat162float(__float2bfloat16(f0));
            float r1 = f1 - __bfloat162float(__float2bfloat16(f1));
            float r2 = f2 - __bfloat162float(__float2bfloat16(f2));
            float r3 = f3 - __bfloat162float(__float2bfloat16(f3));
            *(uint2*)&Bs_h[bb + q * 4] = make_uint2(pack_bf2(f0, f1), pack_bf2(f2, f3));
            *(uint2*)&Bs_l[bb + q * 4] = make_uint2(pack_bf2(r0, r1), pack_bf2(r2, r3));
        }
    };

    gload(0);
    for (int k0 = 0; k0 < Dm; k0 += 16) {
        __syncthreads();
        sstore();
        __syncthreads();
        if (k0 + 16 < Dm) gload(k0 + 16);

        uint32_t ah[4][4], al[4][4], bh[2][4], bl[2][4];
        #pragma unroll
        for (int mi = 0; mi < 4; mi++) {
            uint32_t off = ((wm * 64 + mi * 16 + (lane & 15)) * A_ST) * 2 + (lane >> 4) * 16;
            LDSM4(ah[mi], ash + off);
            LDSM4(al[mi], asl + off);
        }
        #pragma unroll
        for (int nh = 0; nh < 2; nh++) {
            uint32_t off = ((lane & 15) * B_ST + wn * 32 + nh * 16) * 2 + (lane >> 4) * 16;
            LDSM4T(bh[nh], bsh + off);
            LDSM4T(bl[nh], bsl + off);
        }
        #pragma unroll
        for (int mi = 0; mi < 4; mi++)
            #pragma unroll
            for (int nj = 0; nj < 4; nj++) {
                int nh = nj >> 1, oc = (nj & 1) * 2;
                mma_bf16(acc[mi][nj], ah[mi], bh[nh][oc], bh[nh][oc + 1]);
                mma_bf16(acc[mi][nj], ah[mi], bl[nh][oc], bl[nh][oc + 1]);
                mma_bf16(acc[mi][nj], al[mi], bh[nh][oc], bh[nh][oc + 1]);
            }
    }

    const int r = lane >> 2, c2 = (lane & 3) * 2;
    float* C = WHICH ? g_v : g_k;
    #pragma unroll
    for (int mi = 0; mi < 4; mi++) {
        int m_ = m0 + wm * 64 + mi * 16 + r;
        #pragma unroll
        for (int nj = 0; nj < 4; nj++) {
            int n_ = n0 + wn * 32 + nj * 8 + c2;
            float v0 = acc[mi][nj][0], v1 = acc[mi][nj][1];
            float v2 = acc[mi][nj][2], v3 = acc[mi][nj][3];
            if (WHICH == 0) {
                float2 e0 = *(const float2*)&g_e[(size_t)m_ * KD + n_];
                float2 e1 = *(const float2*)&g_e[(size_t)(m_ + 8) * KD + n_];
                v0 *= e0.x; v1 *= e0.y; v2 *= e1.x; v3 *= e1.y;
            }
            *(float2*)&C[(size_t)m_ * N + n_]       = make_float2(v0, v1);
            *(float2*)&C[(size_t)(m_ + 8) * N + n_] = make_float2(v2, v3);
        }
    }
}

// ---------------------------------------------------------------------------
// Kernel 4a (proven): out = initial_state * exp(Gtot)
// ---------------------------------------------------------------------------
__global__ __launch_bounds__(256) void k_init(const float* __restrict__ init,
                                              float* __restrict__ out) {
    int i = blockIdx.x * 256 + threadIdx.x;
    out[i] = init[i] * expf(g_gtot[i >> 8]);
}

// ---------------------------------------------------------------------------
// Kernel 4b (proven): S[bh] += ktilde^T @ v ; split-K atomics (fp32)
// ---------------------------------------------------------------------------
__global__ __launch_bounds__(256) void k_state(float* __restrict__ out) {
    int bh = blockIdx.y;
    int b = bh >> 3, h = bh & 7;
    int tseg0 = blockIdx.z * 256;
    __shared__ __align__(16) float As[16][128];
    __shared__ __align__(16) float Bs[16][128];
    const float* Abase = g_k + (size_t)b * TT * KD + h * 128;
    const float* Bbase = g_v + (size_t)b * TT * VD + h * 256 + blockIdx.x * 128;
    int tid = threadIdx.x;
    int tx = tid & 15, ty = tid >> 4;
    float acc[8][8];
    #pragma unroll
    for (int i = 0; i < 8; i++)
        #pragma unroll
        for (int j = 0; j < 8; j++) acc[i][j] = 0.f;

    for (int t0 = tseg0; t0 < tseg0 + 256; t0 += 16) {
        #pragma unroll
        for (int l = 0; l < 2; l++) {
            int f = tid + l * 256;
            int rr = f >> 5, cc = (f & 31) * 4;
            *(float4*)&As[rr][cc] = *(const float4*)(Abase + (size_t)(t0 + rr) * KD + cc);
            *(float4*)&Bs[rr][cc] = *(const float4*)(Bbase + (size_t)(t0 + rr) * VD + cc);
        }
        __syncthreads();
        #pragma unroll
        for (int tt = 0; tt < 16; tt++) {
            float4 a0 = *(const float4*)&As[tt][ty * 8];
            float4 a1 = *(const float4*)&As[tt][ty * 8 + 4];
            float4 b0 = *(const float4*)&Bs[tt][tx * 8];
            float4 b1 = *(const float4*)&Bs[tt][tx * 8 + 4];
            float a[8] = {a0.x, a0.y, a0.z, a0.w, a1.x, a1.y, a1.z, a1.w};
            float bb[8] = {b0.x, b0.y, b0.z, b0.w, b1.x, b1.y, b1.z, b1.w};
            #pragma unroll
            for (int i = 0; i < 8; i++)
                #pragma unroll
                for (int j = 0; j < 8; j++) acc[i][j] += a[i] * bb[j];
        }
        __syncthreads();
    }
    float* obase = out + (size_t)bh * 128 * 256 + blockIdx.x * 128;
    #pragma unroll
    for (int i = 0; i < 8; i++) {
        int kk = ty * 8 + i;
        #pragma unroll
        for (int j = 0; j < 8; j++)
            atomicAdd(&obase[(size_t)kk * 256 + tx * 8 + j], acc[i][j]);
    }
}

// ---------------------------------------------------------------------------
extern "C" void kernel_launch(void* const* d_in, const int* in_sizes, int n_in,
                              void* d_out, int out_size) {
    const float* seg  = (const float*)d_in[0];
    const float* nw   = (const float*)d_in[1];
    const float* Wk   = (const float*)d_in[2];
    const float* Wv   = (const float*)d_in[3];
    const float* Wg1  = (const float*)d_in[4];
    const float* Wg2  = (const float*)d_in[5];
    const float* bg2  = (const float*)d_in[6];
    const float* init = (const float*)d_in[7];
    float* out = (float*)d_out;

    k_rmsnorm<<<BT, 256>>>(seg, nw, Wg1);
    k_gate1<<<NB * 32, 256>>>(Wg2, bg2);
    k_gate2<<<16, 256>>>();
    k_gate3<<<NB * 32, 256>>>();
    k_mm<0><<<dim3(KD / 128, BT / 128), 256>>>(Wk);
    k_mm<1><<<dim3(VD / 128, BT / 128), 256>>>(Wv);
    k_init<<<(NB * KD * 256) / 256, 256>>>(init, out);
    k_state<<<dim3(2, 32, 8), 256>>>(out);
}